// round 1
// baseline (speedup 1.0000x reference)
#include <cuda_runtime.h>

// Problem shapes (fixed by the reference setup_inputs)
#define BATCH 256
#define TLEN  64
#define NCTX  2048
#define DDIM  128

// Scratch for attention weights [BATCH, NCTX] (2 MB). Static device array per
// allocation rules.
__device__ float g_attn[BATCH * NCTX];

// Kernel 1: per-batch GEMV (ctx @ Wc) * T, then softmax over n, write weights.
// One CTA per batch, 1024 threads (32 warps). Each warp handles rows
// n = warp, warp+32, ... (64 rows per warp). A row's 128 floats are read as
// 32 float4 (one per lane), dotted with Wc held in registers, warp-reduced.
__global__ __launch_bounds__(1024) void scores_softmax_kernel(
    const float* __restrict__ ctx, const float* __restrict__ W) {
    const int b    = blockIdx.x;
    const int tid  = threadIdx.x;
    const int warp = tid >> 5;
    const int lane = tid & 31;

    __shared__ float s[NCTX];       // scores, then exp values
    __shared__ float red[32];       // cross-warp reduction

    // Wc = W[128:256]; lane holds 4 consecutive elements.
    const float4 wc = reinterpret_cast<const float4*>(W + DDIM)[lane];

    const float4* cb =
        reinterpret_cast<const float4*>(ctx) + (size_t)b * NCTX * (DDIM / 4);

    for (int n = warp; n < NCTX; n += 32) {
        float4 v = cb[n * (DDIM / 4) + lane];
        float d = v.x * wc.x + v.y * wc.y + v.z * wc.z + v.w * wc.w;
        #pragma unroll
        for (int o = 16; o > 0; o >>= 1)
            d += __shfl_xor_sync(0xffffffffu, d, o);
        if (lane == 0) s[n] = d * (float)TLEN;
    }
    __syncthreads();

    // Block max over NCTX scores.
    float m = -3.0e38f;
    for (int n = tid; n < NCTX; n += 1024) m = fmaxf(m, s[n]);
    #pragma unroll
    for (int o = 16; o > 0; o >>= 1)
        m = fmaxf(m, __shfl_xor_sync(0xffffffffu, m, o));
    if (lane == 0) red[warp] = m;
    __syncthreads();
    if (warp == 0) {
        float mm = red[lane];
        #pragma unroll
        for (int o = 16; o > 0; o >>= 1)
            mm = fmaxf(mm, __shfl_xor_sync(0xffffffffu, mm, o));
        if (lane == 0) red[0] = mm;
    }
    __syncthreads();
    m = red[0];
    __syncthreads();   // everyone has read red[0] before red is reused below

    // exp + block sum.
    float sum = 0.0f;
    for (int n = tid; n < NCTX; n += 1024) {
        float e = expf(s[n] - m);
        s[n] = e;
        sum += e;
    }
    #pragma unroll
    for (int o = 16; o > 0; o >>= 1)
        sum += __shfl_xor_sync(0xffffffffu, sum, o);
    if (lane == 0) red[warp] = sum;
    __syncthreads();
    if (warp == 0) {
        float ss = red[lane];
        #pragma unroll
        for (int o = 16; o > 0; o >>= 1)
            ss += __shfl_xor_sync(0xffffffffu, ss, o);
        if (lane == 0) red[0] = ss;
    }
    __syncthreads();
    const float inv_sum = 1.0f / red[0];

    float* out_attn = g_attn + (size_t)b * NCTX;
    for (int n = tid; n < NCTX; n += 1024)
        out_attn[n] = s[n] * inv_sum;
}

// Kernel 2: out[b,n,d] = attn[b,n] * ctx[b,n,d], float4-vectorized.
// One float4 per thread. 32 consecutive threads share one attn value (D=128
// floats = 32 float4) -> broadcast load.
__global__ __launch_bounds__(1024) void scale_out_kernel(
    const float* __restrict__ ctx, float* __restrict__ out) {
    const size_t i = (size_t)blockIdx.x * blockDim.x + threadIdx.x;  // float4 idx
    const float a = g_attn[i >> 5];
    float4 v = reinterpret_cast<const float4*>(ctx)[i];
    v.x *= a; v.y *= a; v.z *= a; v.w *= a;
    reinterpret_cast<float4*>(out)[i] = v;
}

extern "C" void kernel_launch(void* const* d_in, const int* in_sizes, int n_in,
                              void* d_out, int out_size) {
    // Inputs: [0] targetsentence_emb (unused), [1] context_emb, [2] W, [3] b (unused)
    const float* ctx = (const float*)d_in[1];
    const float* W   = (const float*)d_in[2];
    float* out       = (float*)d_out;

    scores_softmax_kernel<<<BATCH, 1024>>>(ctx, W);

    const size_t total_f4 = (size_t)BATCH * NCTX * DDIM / 4;  // 16,777,216
    scale_out_kernel<<<(unsigned)(total_f4 / 1024), 1024>>>(ctx, out);
}